// round 2
// baseline (speedup 1.0000x reference)
#include <cuda_runtime.h>
#include <cuda_bf16.h>

// S4D: K[h, l] = 2*Re( sum_n Ck[h,n] * exp(dtA[h,n]*l) ),  H=1024, N2=32, L=4096
//
// Factorization l = a + 64*b:
//   P[n][a] = 2*Ck_n*w^a,  Q[n][b] = (w^64)^b,  w = exp(dt*A)
//   K[a+64b] = sum_n ( Qr*Pr - Qi*Pi )
//
// f32x2 packing over mode pairs: tables stored as float2 with (n even, n odd)
// in (lo, hi); a single fma.rn.f32x2 accumulates two modes at once. Final
// reduce: lo+hi. Qi table stores -qi so the inner loop is pure FFMA2.
//
// Thread (tx,ty) of 16x16 owns a-columns {2tx,2tx+1,2tx+32,2tx+33} and
// b-rows {4ty..4ty+3}: LDS.128 P loads are contiguous 256B per warp
// (conflict-free); Q loads are ty-broadcast.

#define N2C 32
#define NP  16   // mode pairs
#define LL  64

typedef unsigned long long u64;

__device__ __forceinline__ u64 ffma2(u64 a, u64 b, u64 c) {
    u64 d;
    asm("fma.rn.f32x2 %0, %1, %2, %3;" : "=l"(d) : "l"(a), "l"(b), "l"(c));
    return d;
}

__device__ __forceinline__ float f2sum(u64 v) {
    float2 f = *reinterpret_cast<float2*>(&v);
    return f.x + f.y;
}

__global__ __launch_bounds__(256, 3)
void s4d_kernel(const float* __restrict__ log_dt,
                const float* __restrict__ C,
                const float* __restrict__ log_A_real,
                const float* __restrict__ A_imag,
                float* __restrict__ out)
{
    __shared__ __align__(16) float2 PrP[NP][LL];
    __shared__ __align__(16) float2 PiP[NP][LL];
    __shared__ __align__(16) float2 QrP[NP][LL];
    __shared__ __align__(16) float2 QiP[NP][LL];   // holds -qi

    const int h   = blockIdx.x;
    const int tid = threadIdx.x;

    // ---------------- Phase 1: build tables (32 modes x 8 slices) ----------
    {
        const int n  = tid & 31;
        const int s  = tid >> 5;          // slice 0..7 (8 entries each)
        const int n2 = n >> 1;
        const int c  = n & 1;

        const float dt = expf(log_dt[h]);
        const float Ar = -expf(log_A_real[h * N2C + n]);
        const float Ai = A_imag[h * N2C + n];
        const float dr = dt * Ar;
        const float di = dt * Ai;

        // w = exp(dt*A)
        float er = expf(dr), sn, cs;
        sincosf(di, &sn, &cs);
        const float wr = er * cs, wi = er * sn;

        // g = (w-1)/A ;  P0 = 2*C*g
        const float inv = 1.0f / (Ar * Ar + Ai * Ai);
        const float nr = wr - 1.0f, ni = wi;
        const float gr = (nr * Ar + ni * Ai) * inv;
        const float gi = (ni * Ar - nr * Ai) * inv;
        const float Cr = C[(h * N2C + n) * 2 + 0];
        const float Ci = C[(h * N2C + n) * 2 + 1];
        const float p0r = 2.0f * (Cr * gr - Ci * gi);
        const float p0i = 2.0f * (Cr * gi + Ci * gr);

        float* PrF = (float*)PrP;
        float* PiF = (float*)PiP;
        float* QrF = (float*)QrP;
        float* QiF = (float*)QiP;

        // --- P slice: start at w^{8s} (direct), then recurrence by w ---
        {
            const float a0f = (float)(8 * s);
            er = expf(dr * a0f);
            sincosf(di * a0f, &sn, &cs);
            const float wsr = er * cs, wsi = er * sn;
            float pr = p0r * wsr - p0i * wsi;
            float pi = p0r * wsi + p0i * wsr;
            #pragma unroll
            for (int k = 0; k < 8; k++) {
                const int a = 8 * s + k;
                PrF[(n2 * LL + a) * 2 + c] = pr;
                PiF[(n2 * LL + a) * 2 + c] = pi;
                const float t = pr * wr - pi * wi;
                pi = pr * wi + pi * wr;
                pr = t;
            }
        }

        // --- Q slice: start at (w^64)^{8s} = exp(512*s*dtA) (direct) ---
        {
            er = expf(64.0f * dr);
            sincosf(64.0f * di, &sn, &cs);
            const float wJr = er * cs, wJi = er * sn;

            const float b0f = 512.0f * (float)s;
            er = expf(dr * b0f);
            sincosf(di * b0f, &sn, &cs);
            float qr = er * cs, qi = er * sn;
            #pragma unroll
            for (int k = 0; k < 8; k++) {
                const int b = 8 * s + k;
                QrF[(n2 * LL + b) * 2 + c] =  qr;
                QiF[(n2 * LL + b) * 2 + c] = -qi;
                const float t = qr * wJr - qi * wJi;
                qi = qr * wJi + qi * wJr;
                qr = t;
            }
        }
    }
    __syncthreads();

    // ---------------- Phase 2: 64x64 contraction, f32x2 over mode pairs ----
    const int tx = tid & 15;
    const int ty = tid >> 4;
    const int b0 = ty * 4;
    const int aA = 2 * tx;        // a-columns aA, aA+1
    const int aB = 2 * tx + 32;   // a-columns aB, aB+1

    u64 acc[4][4];
    #pragma unroll
    for (int i = 0; i < 4; i++)
        #pragma unroll
        for (int j = 0; j < 4; j++)
            acc[i][j] = 0ull;

    #pragma unroll
    for (int n2 = 0; n2 < NP; n2++) {
        // -------- real half: acc += qr * pr --------
        {
            const ulonglong2 q0 = *(const ulonglong2*)&QrP[n2][b0];
            const ulonglong2 q1 = *(const ulonglong2*)&QrP[n2][b0 + 2];
            const ulonglong2 p0 = *(const ulonglong2*)&PrP[n2][aA];
            const ulonglong2 p1 = *(const ulonglong2*)&PrP[n2][aB];
            const u64 qr[4] = {q0.x, q0.y, q1.x, q1.y};
            const u64 pr[4] = {p0.x, p0.y, p1.x, p1.y};
            #pragma unroll
            for (int i = 0; i < 4; i++)
                #pragma unroll
                for (int j = 0; j < 4; j++)
                    acc[i][j] = ffma2(qr[i], pr[j], acc[i][j]);
        }
        // -------- imag half: acc += (-qi) * pi --------
        {
            const ulonglong2 q0 = *(const ulonglong2*)&QiP[n2][b0];
            const ulonglong2 q1 = *(const ulonglong2*)&QiP[n2][b0 + 2];
            const ulonglong2 p0 = *(const ulonglong2*)&PiP[n2][aA];
            const ulonglong2 p1 = *(const ulonglong2*)&PiP[n2][aB];
            const u64 qi[4] = {q0.x, q0.y, q1.x, q1.y};
            const u64 pi[4] = {p0.x, p0.y, p1.x, p1.y};
            #pragma unroll
            for (int i = 0; i < 4; i++)
                #pragma unroll
                for (int j = 0; j < 4; j++)
                    acc[i][j] = ffma2(qi[i], pi[j], acc[i][j]);
        }
    }

    // ---------------- Store: reduce mode pairs, STG.64 coalesced ----------
    float* o = out + (size_t)h * (LL * LL);
    #pragma unroll
    for (int i = 0; i < 4; i++) {
        float* row = o + (b0 + i) * LL;
        float2 vA = make_float2(f2sum(acc[i][0]), f2sum(acc[i][1]));
        float2 vB = make_float2(f2sum(acc[i][2]), f2sum(acc[i][3]));
        *reinterpret_cast<float2*>(row + aA) = vA;
        *reinterpret_cast<float2*>(row + aB) = vB;
    }
}

extern "C" void kernel_launch(void* const* d_in, const int* in_sizes, int n_in,
                              void* d_out, int out_size)
{
    const float* log_dt     = (const float*)d_in[0];
    const float* C          = (const float*)d_in[1];
    const float* log_A_real = (const float*)d_in[2];
    const float* A_imag     = (const float*)d_in[3];
    float*       out        = (float*)d_out;

    const int H = in_sizes[0];   // 1024
    s4d_kernel<<<H, 256>>>(log_dt, C, log_A_real, A_imag, out);
}

// round 3
// speedup vs baseline: 1.4985x; 1.4985x over previous
#include <cuda_runtime.h>
#include <cuda_bf16.h>

// S4D: K[h, a+64b] = sum_n ( Qr[n][b]*Pr[n][a] - Qi[n][b]*Pi[n][a] )
//   P[n][a] = 2*Ck_n*w^a,  Q[n][b] = (w^64)^b,  w = exp(dt*A)
//
// Tables stored as float2 (mode-pair packed) with a bank-conflict-killing
// XOR swizzle on the column index: col' = col ^ ((n2&7)<<1). Preserves
// float2 pairing (bit0) and 16B alignment (even cols stay even), and maps
// the n2 row index into the bank bits so phase-1 STS are ~conflict-free.
//
// 128 threads/block: phase 1 = 16 mode-pairs x 8 slices (both modes per
// thread, float2 stores). Phase 2 = 16(tx: a) x 8(ty: b) threads, each an
// 8b x 4a register tile; Q loads are warp-broadcast (cheap), P loads are
// contiguous 256B per warp.

#define NP 16
#define LL 64

typedef unsigned long long u64;

__device__ __forceinline__ u64 ffma2(u64 a, u64 b, u64 c) {
    u64 d;
    asm("fma.rn.f32x2 %0, %1, %2, %3;" : "=l"(d) : "l"(a), "l"(b), "l"(c));
    return d;
}
__device__ __forceinline__ float f2sum(u64 v) {
    float2 f = *reinterpret_cast<float2*>(&v);
    return f.x + f.y;
}

__global__ __launch_bounds__(128, 3)
void s4d_kernel(const float* __restrict__ log_dt,
                const float* __restrict__ C,
                const float* __restrict__ log_A_real,
                const float* __restrict__ A_imag,
                float* __restrict__ out)
{
    __shared__ __align__(16) float2 PrP[NP][LL];
    __shared__ __align__(16) float2 PiP[NP][LL];
    __shared__ __align__(16) float2 QrP[NP][LL];
    __shared__ __align__(16) float2 QiP[NP][LL];   // holds -qi

    const int h   = blockIdx.x;
    const int tid = threadIdx.x;

    // ---------------- Phase 1: build tables ----------------
    {
        const int n2 = tid & 15;
        const int s  = tid >> 4;          // slice 0..7 (8 entries each)
        const int xr = (n2 & 7) << 1;     // column swizzle
        const float dt = expf(log_dt[h]);

        float wr[2], wi[2], pr[2], pi[2], wJr[2], wJi[2], qr[2], qi[2];
        #pragma unroll
        for (int c = 0; c < 2; c++) {
            const int m = 2 * n2 + c;
            const float Ar = -expf(log_A_real[h * 32 + m]);
            const float Ai = A_imag[h * 32 + m];
            const float dr = dt * Ar, di = dt * Ai;

            float er, sn, cs;
            er = expf(dr); sincosf(di, &sn, &cs);
            wr[c] = er * cs; wi[c] = er * sn;

            const float inv = 1.0f / (Ar * Ar + Ai * Ai);
            const float nr = wr[c] - 1.0f, ni = wi[c];
            const float gr = (nr * Ar + ni * Ai) * inv;
            const float gi = (ni * Ar - nr * Ai) * inv;
            const float Cr = C[(h * 32 + m) * 2 + 0];
            const float Ci = C[(h * 32 + m) * 2 + 1];
            const float p0r = 2.0f * (Cr * gr - Ci * gi);
            const float p0i = 2.0f * (Cr * gi + Ci * gr);

            // P slice start: p = P0 * w^{8s} (direct eval)
            const float a0f = (float)(8 * s);
            er = expf(dr * a0f); sincosf(di * a0f, &sn, &cs);
            const float wsr = er * cs, wsi = er * sn;
            pr[c] = p0r * wsr - p0i * wsi;
            pi[c] = p0r * wsi + p0i * wsr;

            // wJ = w^64 (direct)
            er = expf(64.0f * dr); sincosf(64.0f * di, &sn, &cs);
            wJr[c] = er * cs; wJi[c] = er * sn;

            // Q slice start: q = (w^64)^{8s} = exp(512*s*dtA) (direct)
            const float b0f = 512.0f * (float)s;
            er = expf(dr * b0f); sincosf(di * b0f, &sn, &cs);
            qr[c] = er * cs; qi[c] = er * sn;
        }

        #pragma unroll
        for (int k = 0; k < 8; k++) {
            const int col = (8 * s + k) ^ xr;
            PrP[n2][col] = make_float2(pr[0], pr[1]);
            PiP[n2][col] = make_float2(pi[0], pi[1]);
            QrP[n2][col] = make_float2(qr[0], qr[1]);
            QiP[n2][col] = make_float2(-qi[0], -qi[1]);
            #pragma unroll
            for (int c = 0; c < 2; c++) {
                float t;
                t = pr[c] * wr[c] - pi[c] * wi[c];
                pi[c] = pr[c] * wi[c] + pi[c] * wr[c];
                pr[c] = t;
                t = qr[c] * wJr[c] - qi[c] * wJi[c];
                qi[c] = qr[c] * wJi[c] + qi[c] * wJr[c];
                qr[c] = t;
            }
        }
    }
    __syncthreads();

    // ---------------- Phase 2: 64x64 contraction, 8b x 4a tiles ----------
    const int tx = tid & 15;
    const int ty = tid >> 4;          // 0..7
    const int b0 = 8 * ty;
    const int aA = 2 * tx;            // owns a in {aA, aA+1, aA+32, aA+33}

    u64 acc[8][4];
    #pragma unroll
    for (int i = 0; i < 8; i++)
        #pragma unroll
        for (int j = 0; j < 4; j++)
            acc[i][j] = 0ull;

    #pragma unroll
    for (int n2 = 0; n2 < NP; n2++) {
        const int x  = (n2 & 7) << 1;
        const int cA = aA ^ x;        // even; cA+32 covers the aB pair

        // -------- real half: acc += qr * pr --------
        {
            const ulonglong2 pA = *(const ulonglong2*)&PrP[n2][cA];
            const ulonglong2 pB = *(const ulonglong2*)&PrP[n2][cA + 32];
            const u64 p[4] = {pA.x, pA.y, pB.x, pB.y};
            u64 q[8];
            #pragma unroll
            for (int k = 0; k < 4; k++) {
                const ulonglong2 t = *(const ulonglong2*)&QrP[n2][(b0 + 2 * k) ^ x];
                q[2 * k] = t.x; q[2 * k + 1] = t.y;
            }
            #pragma unroll
            for (int i = 0; i < 8; i++)
                #pragma unroll
                for (int j = 0; j < 4; j++)
                    acc[i][j] = ffma2(q[i], p[j], acc[i][j]);
        }
        // -------- imag half: acc += (-qi) * pi --------
        {
            const ulonglong2 pA = *(const ulonglong2*)&PiP[n2][cA];
            const ulonglong2 pB = *(const ulonglong2*)&PiP[n2][cA + 32];
            const u64 p[4] = {pA.x, pA.y, pB.x, pB.y};
            u64 q[8];
            #pragma unroll
            for (int k = 0; k < 4; k++) {
                const ulonglong2 t = *(const ulonglong2*)&QiP[n2][(b0 + 2 * k) ^ x];
                q[2 * k] = t.x; q[2 * k + 1] = t.y;
            }
            #pragma unroll
            for (int i = 0; i < 8; i++)
                #pragma unroll
                for (int j = 0; j < 4; j++)
                    acc[i][j] = ffma2(q[i], p[j], acc[i][j]);
        }
    }

    // ---------------- Store: reduce mode pairs, STG.64 coalesced ----------
    float* o = out + (size_t)h * (LL * LL);
    #pragma unroll
    for (int i = 0; i < 8; i++) {
        float* row = o + (b0 + i) * LL;
        *reinterpret_cast<float2*>(row + aA) =
            make_float2(f2sum(acc[i][0]), f2sum(acc[i][1]));
        *reinterpret_cast<float2*>(row + aA + 32) =
            make_float2(f2sum(acc[i][2]), f2sum(acc[i][3]));
    }
}

extern "C" void kernel_launch(void* const* d_in, const int* in_sizes, int n_in,
                              void* d_out, int out_size)
{
    const float* log_dt     = (const float*)d_in[0];
    const float* C          = (const float*)d_in[1];
    const float* log_A_real = (const float*)d_in[2];
    const float* A_imag     = (const float*)d_in[3];
    float*       out        = (float*)d_out;

    const int H = in_sizes[0];   // 1024
    s4d_kernel<<<H, 128>>>(log_dt, C, log_A_real, A_imag, out);
}